// round 8
// baseline (speedup 1.0000x reference)
#include <cuda_runtime.h>
#include <cuda_bf16.h>
#include <math.h>
#include <stdint.h>

#define NROWS 4096
#define NC    256
#define TM    128           // rows per fused block
#define KT    16            // k per pipeline stage

// smem layout (bytes)
// stage: Ahi 128x48 | Alo 128x48 | Whi 256x48 | Wlo 256x48 = 36864
#define STG   36864
#define A_HI  0
#define A_LO  6144
#define W_HI  12288
#define W_LO  24576
#define SH_HI 73728          // H hi: 128 rows x 528B
#define SH_LO 141312
#define RS_OFF 208896        // rowsum[128]
#define SMEM_TOTAL 209408

// ---------------- scratch ----------------
__device__ __align__(16) __nv_bfloat16 g_Xhi[4096 * 1792];
__device__ __align__(16) __nv_bfloat16 g_Xlo[4096 * 1792];
__device__ __align__(16) __nv_bfloat16 g_W1hi[1792 * 256];
__device__ __align__(16) __nv_bfloat16 g_W1lo[1792 * 256];
__device__ __align__(16) __nv_bfloat16 g_W2hi[3 * 256 * 256];
__device__ __align__(16) __nv_bfloat16 g_W2lo[3 * 256 * 256];

// ---------------- asm helpers ----------------
__device__ __forceinline__ uint32_t smem_u32(const void* p) {
    uint32_t a;
    asm("{ .reg .u64 t; cvta.to.shared.u64 t, %1; cvt.u32.u64 %0, t; }" : "=r"(a) : "l"(p));
    return a;
}
#define LDSM_X4(r0, r1, r2, r3, addr) \
    asm volatile("ldmatrix.sync.aligned.m8n8.x4.shared.b16 {%0,%1,%2,%3}, [%4];" \
        : "=r"(r0), "=r"(r1), "=r"(r2), "=r"(r3) : "r"(addr))
#define MMA16816(d, a, b0v, b1v) \
    asm volatile("mma.sync.aligned.m16n8k16.row.col.f32.bf16.bf16.f32 " \
        "{%0,%1,%2,%3}, {%4,%5,%6,%7}, {%8,%9}, {%0,%1,%2,%3};" \
        : "+f"((d)[0]), "+f"((d)[1]), "+f"((d)[2]), "+f"((d)[3]) \
        : "r"((a)[0]), "r"((a)[1]), "r"((a)[2]), "r"((a)[3]), "r"(b0v), "r"(b1v))
#define CP16(dst, src) \
    asm volatile("cp.async.cg.shared.global [%0], [%1], 16;" :: "r"(dst), "l"(src))
#define CP_COMMIT() asm volatile("cp.async.commit_group;" ::: "memory")
#define CP_WAIT0()  asm volatile("cp.async.wait_group 0;" ::: "memory")
#define CP_WAIT1()  asm volatile("cp.async.wait_group 1;" ::: "memory")

// ---------------- prep kernel: gather (MLP=8) + weight transform ----------------
struct PrepParams {
    const float* feat[3];
    const void*  pid[3];
    const float* W1[3];
    const float* W2[3];
    int    C[3];
    int    HW[3];
    size_t xoff[3];
    size_t w1off[3];
};

__global__ void prep_kernel(PrepParams p) {
    const int lvl = blockIdx.z;
    const int C   = p.C[lvl];
    const int bx  = blockIdx.x;
    const int tid = threadIdx.x;

    if (bx < 512) {
        // ---- gather: 8 rows per block, warp per row, 8 outstanding loads/lane ----
        const int wid = tid >> 5, lane = tid & 31;
        const int row = bx * 8 + wid;
        const int HW = p.HW[lvl];
        const int* pw = (const int*)p.pid[lvl];
        bool i64 = true;
#pragma unroll
        for (int i = 1; i < 64; i += 2) i64 = i64 && (pw[i] == 0);
        long long pid = i64 ? ((const long long*)p.pid[lvl])[row & 255]
                            : (long long)pw[row & 255];
        if (pid < 0)  pid = 0;
        if (pid >= HW) pid = HW - 1;
        const float* src = p.feat[lvl] + (size_t)(row >> 8) * C * HW + (size_t)pid;
        const size_t d0 = p.xoff[lvl] + (size_t)row * C;
        for (int c = lane; c < C; c += 256) {
            float x[8];
#pragma unroll
            for (int j = 0; j < 8; j++) x[j] = src[(size_t)(c + 32 * j) * HW];
#pragma unroll
            for (int j = 0; j < 8; j++) {
                __nv_bfloat16 h = __float2bfloat16(x[j]);
                __nv_bfloat16 l = __float2bfloat16(x[j] - __bfloat162float(h));
                g_Xhi[d0 + c + 32 * j] = h;
                g_Xlo[d0 + c + 32 * j] = l;
            }
        }
        return;
    }

    // ---- weight transform: W[K,256] -> [N=256,K] hi/lo ----
    const int t1 = bx - 512;
    const int nW1 = 8 * (C / 32);
    const float* W;
    __nv_bfloat16 *oh, *ol;
    int K, nb, kb;
    if (t1 < nW1) {
        W = p.W1[lvl]; K = C;
        oh = g_W1hi + p.w1off[lvl]; ol = g_W1lo + p.w1off[lvl];
        nb = (t1 & 7) * 32; kb = (t1 >> 3) * 32;
    } else {
        const int t2 = t1 - nW1;
        if (t2 >= 64) return;
        W = p.W2[lvl]; K = NC;
        oh = g_W2hi + (size_t)lvl * 256 * 256; ol = g_W2lo + (size_t)lvl * 256 * 256;
        nb = (t2 & 7) * 32; kb = (t2 >> 3) * 32;
    }
    const int tx = tid & 31, ty = tid >> 5;
    __shared__ float t[32][33];
    for (int i = ty; i < 32; i += 8)
        t[i][tx] = W[(size_t)(kb + i) * NC + nb + tx];
    __syncthreads();
    for (int i = ty; i < 32; i += 8) {
        float x = t[tx][i];
        __nv_bfloat16 h = __float2bfloat16(x);
        __nv_bfloat16 l = __float2bfloat16(x - __bfloat162float(h));
        oh[(size_t)(nb + i) * K + kb + tx] = h;
        ol[(size_t)(nb + i) * K + kb + tx] = l;
    }
}

// ---------------- fused MLP (layer1 + layer2 + l2norm), TM=128, 512 thr ----------------
struct FusedParams {
    const float* bias1[3];
    const float* bias2[3];
    int    K[3];
    size_t xoff[3];
    size_t w1off[3];
    float* out;
};

// warp tile 32(M) x 64(N); B processed in two 32-col halves to limit regs
__device__ __forceinline__ void mma_step(
    uint32_t aHi, uint32_t aLo, int strA, int lcA,
    uint32_t wHi, uint32_t wLo, int lr, int lcW,
    float (&acc)[2][8][4])
{
    uint32_t ah[2][4], al[2][4];
#pragma unroll
    for (int mt = 0; mt < 2; mt++) {
        const uint32_t ro = (mt * 16 + lr) * strA + lcA;
        LDSM_X4(ah[mt][0], ah[mt][1], ah[mt][2], ah[mt][3], aHi + ro);
        LDSM_X4(al[mt][0], al[mt][1], al[mt][2], al[mt][3], aLo + ro);
    }
#pragma unroll
    for (int go = 0; go < 2; go++) {
        uint32_t bh[2][4], bl[2][4];
#pragma unroll
        for (int g = 0; g < 2; g++) {
            const uint32_t ro = ((go * 2 + g) * 16 + lr) * 48 + lcW;
            LDSM_X4(bh[g][0], bh[g][1], bh[g][2], bh[g][3], wHi + ro);
            LDSM_X4(bl[g][0], bl[g][1], bl[g][2], bl[g][3], wLo + ro);
        }
#pragma unroll
        for (int mt = 0; mt < 2; mt++)
#pragma unroll
            for (int nl = 0; nl < 4; nl++) {
                const int nb = go * 4 + nl;
                const int g = nl >> 1, h = nl & 1;
                MMA16816(acc[mt][nb], ah[mt], bh[g][h], bh[g][h + 2]);
                MMA16816(acc[mt][nb], ah[mt], bl[g][h], bl[g][h + 2]);
                MMA16816(acc[mt][nb], al[mt], bh[g][h], bh[g][h + 2]);
            }
    }
}

__global__ void __launch_bounds__(512, 1) fused_mlp_kernel(FusedParams p) {
    extern __shared__ __align__(16) char dsm[];
    const uint32_t sb = smem_u32(dsm);

    const int lvl = blockIdx.z;
    const int K = p.K[lvl];
    const int rowBase = blockIdx.x * TM;
    const int tid = threadIdx.x;
    const int wid = tid >> 5;
    const int lid = tid & 31;
    const int lr  = lid & 15;
    const int lcx = (lid >> 4) * 16;
    const int warpM = (wid >> 2) * 32;
    const int warpN = (wid & 3) * 64;

    const __nv_bfloat16* Ah = g_Xhi + p.xoff[lvl] + (size_t)rowBase * K;
    const __nv_bfloat16* Al = g_Xlo + p.xoff[lvl] + (size_t)rowBase * K;
    const __nv_bfloat16* W1h = g_W1hi + p.w1off[lvl];
    const __nv_bfloat16* W1l = g_W1lo + p.w1off[lvl];
    const __nv_bfloat16* W2h = g_W2hi + (size_t)lvl * 256 * 256;
    const __nv_bfloat16* W2l = g_W2lo + (size_t)lvl * 256 * 256;

    if (tid < 128) *(float*)(dsm + RS_OFF + tid * 4) = 0.0f;

    // ---- stage loaders (512 threads) ----
    auto load1 = [&](int t, int buf) {
        const int k0 = t * KT;
        const uint32_t base = sb + buf * STG;
        {   // A: 512 jobs, 1/thread
            const int half = tid >> 8, rc = tid & 255, r = rc >> 1, ch = rc & 1;
            const __nv_bfloat16* s = (half ? Al : Ah) + (size_t)r * K + k0 + ch * 8;
            CP16(base + (half ? A_LO : A_HI) + r * 48 + ch * 16, s);
        }
#pragma unroll
        for (int j = 0; j < 2; j++) {   // W: 1024 jobs, 2/thread
            const int job = tid + 512 * j;
            const int half = job >> 9, rc = job & 511, n = rc >> 1, ch = rc & 1;
            const __nv_bfloat16* s = (half ? W1l : W1h) + (size_t)n * K + k0 + ch * 8;
            CP16(base + (half ? W_LO : W_HI) + n * 48 + ch * 16, s);
        }
        CP_COMMIT();
    };
    auto load2 = [&](int t, int buf) {
        const int k0 = t * KT;
        const uint32_t base = sb + buf * STG;
#pragma unroll
        for (int j = 0; j < 2; j++) {
            const int job = tid + 512 * j;
            const int half = job >> 9, rc = job & 511, n = rc >> 1, ch = rc & 1;
            const __nv_bfloat16* s = (half ? W2l : W2h) + (size_t)n * 256 + k0 + ch * 8;
            CP16(base + (half ? W_LO : W_HI) + n * 48 + ch * 16, s);
        }
        CP_COMMIT();
    };

    float acc[2][8][4];
#pragma unroll
    for (int mt = 0; mt < 2; mt++)
#pragma unroll
        for (int nb = 0; nb < 8; nb++)
#pragma unroll
            for (int j = 0; j < 4; j++) acc[mt][nb][j] = 0.0f;

    // ================= layer 1 =================
    const int nk1 = K / KT;    // 16 / 32 / 64 (even)
    load1(0, 0);
    for (int t = 0; t < nk1; t++) {
        const int buf = t & 1;
        if (t + 1 < nk1) { load1(t + 1, buf ^ 1); CP_WAIT1(); } else { CP_WAIT0(); }
        __syncthreads();
        const uint32_t base = sb + buf * STG;
        mma_step(base + A_HI + warpM * 48, base + A_LO + warpM * 48, 48, lcx,
                 base + W_HI + warpN * 48, base + W_LO + warpN * 48, lr, lcx, acc);
        __syncthreads();
    }

    // epilogue 1: bias + relu -> H hi/lo smem; prefetch layer2 stage 0 (buf0 free: nk1 even)
    load2(0, 0);
    {
        const float* b1 = p.bias1[lvl];
#pragma unroll
        for (int mt = 0; mt < 2; mt++)
#pragma unroll
            for (int nb = 0; nb < 8; nb++) {
                const int c = warpN + (lid & 3) * 2 + nb * 8;
                const float bx = b1[c], by = b1[c + 1];
#pragma unroll
                for (int hr = 0; hr < 2; hr++) {
                    const int r = warpM + mt * 16 + hr * 8 + (lid >> 2);
                    float v0 = fmaxf(acc[mt][nb][hr * 2]     + bx, 0.0f);
                    float v1 = fmaxf(acc[mt][nb][hr * 2 + 1] + by, 0.0f);
                    __nv_bfloat16 h0 = __float2bfloat16(v0);
                    __nv_bfloat16 h1 = __float2bfloat16(v1);
                    __nv_bfloat162 hv, lv;
                    hv.x = h0; hv.y = h1;
                    lv.x = __float2bfloat16(v0 - __bfloat162float(h0));
                    lv.y = __float2bfloat16(v1 - __bfloat162float(h1));
                    *(__nv_bfloat162*)(dsm + SH_HI + r * 528 + c * 2) = hv;
                    *(__nv_bfloat162*)(dsm + SH_LO + r * 528 + c * 2) = lv;
                }
            }
    }
#pragma unroll
    for (int mt = 0; mt < 2; mt++)
#pragma unroll
        for (int nb = 0; nb < 8; nb++)
#pragma unroll
            for (int j = 0; j < 4; j++) acc[mt][nb][j] = 0.0f;

    // ================= layer 2 ================= (K2 = 256, 16 stages)
    for (int t = 0; t < 16; t++) {
        const int buf = t & 1;
        if (t + 1 < 16) { load2(t + 1, buf ^ 1); CP_WAIT1(); } else { CP_WAIT0(); }
        __syncthreads();
        const uint32_t base = sb + buf * STG;
        mma_step(sb + SH_HI + warpM * 528, sb + SH_LO + warpM * 528, 528, t * 32 + lcx,
                 base + W_HI + warpN * 48, base + W_LO + warpN * 48, lr, lcx, acc);
        __syncthreads();
    }

    // epilogue 2: bias, rowwise sum-of-squares, normalize, store
    {
        const float* b2 = p.bias2[lvl];
        float* rowsum = (float*)(dsm + RS_OFF);
#pragma unroll
        for (int mt = 0; mt < 2; mt++)
#pragma unroll
            for (int hr = 0; hr < 2; hr++) {
                float part = 0.0f;
#pragma unroll
                for (int nb = 0; nb < 8; nb++) {
                    const int c = warpN + (lid & 3) * 2 + nb * 8;
                    float v0 = acc[mt][nb][hr * 2]     + b2[c];
                    float v1 = acc[mt][nb][hr * 2 + 1] + b2[c + 1];
                    acc[mt][nb][hr * 2]     = v0;
                    acc[mt][nb][hr * 2 + 1] = v1;
                    part += v0 * v0 + v1 * v1;
                }
                atomicAdd(&rowsum[warpM + mt * 16 + hr * 8 + (lid >> 2)], part);
            }
        __syncthreads();
        float* O = p.out + (size_t)lvl * NROWS * NC;
#pragma unroll
        for (int mt = 0; mt < 2; mt++)
#pragma unroll
            for (int hr = 0; hr < 2; hr++) {
                const int r = warpM + mt * 16 + hr * 8 + (lid >> 2);
                const float sc = 1.0f / (sqrtf(rowsum[r]) + 1e-7f);
#pragma unroll
                for (int nb = 0; nb < 8; nb++) {
                    const int c = warpN + (lid & 3) * 2 + nb * 8;
                    float2 o;
                    o.x = acc[mt][nb][hr * 2]     * sc;
                    o.y = acc[mt][nb][hr * 2 + 1] * sc;
                    *(float2*)(O + (size_t)(rowBase + r) * NC + c) = o;
                }
            }
    }
}

// ---------------- host ----------------
#define F0 67108864LL
#define F1 33554432LL
#define F2 16777216LL
#define W10 65536LL
#define W11 131072LL
#define W12 262144LL
#define SB  256LL

static inline bool ok_sz(long long actual, long long elems) {
    return actual == elems || actual == elems * 4 || actual == elems * 8;
}

extern "C" void kernel_launch(void* const* d_in, const int* in_sizes, int n_in,
                              void* d_out, int out_size) {
    (void)out_size;
    static const int CS[3]  = {256, 512, 1024};
    static const int HWS[3] = {128 * 128, 64 * 64, 32 * 32};
    static const size_t XOFF[3] = {0, (size_t)4096 * 256, (size_t)4096 * 768};
    static const size_t WOFF[3] = {0, (size_t)256 * 256, (size_t)256 * 768};

    static bool s_attr = false;
    if (!s_attr) {
        cudaFuncSetAttribute(fused_mlp_kernel,
                             cudaFuncAttributeMaxDynamicSharedMemorySize, SMEM_TOTAL);
        s_attr = true;
    }

    static const int ORD_DICT[18]  = { 0,1,2,3,4,5,  6,7,8,9,10,11,  12,13,14,15,16,17 };
    static const int ORD_SIG[18]   = { 0,3,6,7,8,9,  1,4,10,11,12,13,  2,5,14,15,16,17 };
    static const int ORD_ALPHA[18] = { 6,9,12,0,15,3,  7,10,13,1,16,4,  8,11,14,2,17,5 };

    const long long featsz[3] = { F0, F1, F2 };
    const long long w1sz[3]   = { W10, W11, W12 };

    const int* cand[3] = { ORD_DICT, ORD_SIG, ORD_ALPHA };
    const int* ord = nullptr;
    for (int c = 0; c < 3 && !ord; c++) {
        bool ok = (n_in >= 18);
        for (int l = 0; l < 3 && ok; l++) {
            const int* m = cand[c] + 6 * l;
            ok = ok && ok_sz(in_sizes[m[0]], featsz[l])
                    && ok_sz(in_sizes[m[1]], SB)
                    && ok_sz(in_sizes[m[2]], w1sz[l])
                    && ok_sz(in_sizes[m[3]], SB)
                    && ok_sz(in_sizes[m[4]], W10)
                    && ok_sz(in_sizes[m[5]], SB);
        }
        if (ok) ord = cand[c];
    }

    int fi[3] = {-1,-1,-1}, pi[3] = {-1,-1,-1}, w1i[3] = {-1,-1,-1};
    int b1i[3] = {-1,-1,-1}, w2i[3] = {-1,-1,-1}, b2i[3] = {-1,-1,-1};
    if (ord) {
        for (int l = 0; l < 3; l++) {
            const int* m = ord + 6 * l;
            fi[l] = m[0]; pi[l] = m[1]; w1i[l] = m[2];
            b1i[l] = m[3]; w2i[l] = m[4]; b2i[l] = m[5];
        }
    } else {
        int any256 = -1, w2seen = 0, w10seen = 0;
        for (int i = 0; i < n_in; i++) {
            long long s = in_sizes[i];
            if      (ok_sz(s, F0))  fi[0] = i;
            else if (ok_sz(s, F1))  fi[1] = i;
            else if (ok_sz(s, F2))  fi[2] = i;
            else if (ok_sz(s, W11)) w1i[1] = i;
            else if (ok_sz(s, W12)) w1i[2] = i;
            else if (ok_sz(s, W10)) {
                if (!w10seen) { w1i[0] = i; w10seen = 1; }
                else if (w2seen < 3) w2i[w2seen++] = i;
            }
            else if (ok_sz(s, SB) && any256 < 0) any256 = i;
        }
        for (int l = 0; l < 3; l++) {
            if (fi[l] >= 0) {
                int nxt = fi[l] + 1;
                pi[l] = (nxt < n_in && ok_sz(in_sizes[nxt], SB)) ? nxt : any256;
            }
            b1i[l] = any256; b2i[l] = any256;
        }
    }
    for (int l = 0; l < 3; l++) {
        if (fi[l] < 0 || pi[l] < 0 || w1i[l] < 0 || b1i[l] < 0 ||
            w2i[l] < 0 || b2i[l] < 0) return;
    }

    PrepParams pp;
    for (int i = 0; i < 3; i++) {
        pp.feat[i] = (const float*)d_in[fi[i]];
        pp.pid[i]  = d_in[pi[i]];
        pp.W1[i]   = (const float*)d_in[w1i[i]];
        pp.W2[i]   = (const float*)d_in[w2i[i]];
        pp.C[i]    = CS[i];
        pp.HW[i]   = HWS[i];
        pp.xoff[i] = XOFF[i];
        pp.w1off[i] = WOFF[i];
    }

    FusedParams fp;
    for (int i = 0; i < 3; i++) {
        fp.bias1[i] = (const float*)d_in[b1i[i]];
        fp.bias2[i] = (const float*)d_in[b2i[i]];
        fp.K[i]     = CS[i];
        fp.xoff[i]  = XOFF[i];
        fp.w1off[i] = WOFF[i];
    }
    fp.out = (float*)d_out;

    // prep: 512 gather blocks + up to 256 W1 tiles + 64 W2 tiles
    prep_kernel<<<dim3(512 + 256 + 64, 1, 3), 256>>>(pp);

    fused_mlp_kernel<<<dim3(NROWS / TM, 1, 3), 512, SMEM_TOTAL>>>(fp);
}

// round 10
// speedup vs baseline: 1.3134x; 1.3134x over previous
#include <cuda_runtime.h>
#include <cuda_fp16.h>
#include <math.h>
#include <stdint.h>

#define NROWS 4096
#define NC    256
#define TM    64            // rows per fused block
#define KT    32            // k per pipeline stage

// smem layout (bytes); all section bases 16B aligned
#define STG    25600        // stage: A 64x80 | W 256x80
#define A_OFF  0
#define W_OFF  5120
#define H_OFF  51200        // H: 64 rows x 528B (256 fp16 + pad)
#define RS_OFF 84992        // rowsum[64] float
#define SRC_OFF 85248       // srcbase[64] size_t
#define SMEM_TOTAL 85760

// ---------------- scratch: fp16 weights, TRANSPOSED [N=256, K] layout ----------------
__device__ __align__(16) __half g_W1h[256 * 1792];
__device__ __align__(16) __half g_W2h[3 * 256 * 256];

// ---------------- asm helpers ----------------
__device__ __forceinline__ uint32_t smem_u32(const void* p) {
    uint32_t a;
    asm("{ .reg .u64 t; cvta.to.shared.u64 t, %1; cvt.u32.u64 %0, t; }" : "=r"(a) : "l"(p));
    return a;
}
#define LDSM_X4(r0, r1, r2, r3, addr) \
    asm volatile("ldmatrix.sync.aligned.m8n8.x4.shared.b16 {%0,%1,%2,%3}, [%4];" \
        : "=r"(r0), "=r"(r1), "=r"(r2), "=r"(r3) : "r"(addr))
#define MMA16816(d, a, b0v, b1v) \
    asm volatile("mma.sync.aligned.m16n8k16.row.col.f32.f16.f16.f32 " \
        "{%0,%1,%2,%3}, {%4,%5,%6,%7}, {%8,%9}, {%0,%1,%2,%3};" \
        : "+f"((d)[0]), "+f"((d)[1]), "+f"((d)[2]), "+f"((d)[3]) \
        : "r"((a)[0]), "r"((a)[1]), "r"((a)[2]), "r"((a)[3]), "r"(b0v), "r"(b1v))
#define CP16(dst, src) \
    asm volatile("cp.async.cg.shared.global [%0], [%1], 16;" :: "r"(dst), "l"(src))
#define CP_COMMIT() asm volatile("cp.async.commit_group;" ::: "memory")
#define CP_WAIT0()  asm volatile("cp.async.wait_group 0;" ::: "memory")
#define CP_WAIT1()  asm volatile("cp.async.wait_group 1;" ::: "memory")

// ---------------- weight convert: fp32 [K,256] -> fp16 [256,K] (transpose) ----------------
struct WcvtParams {
    const float* W1[3];
    const float* W2[3];
    int    K[3];
    size_t w1off[3];
};

__global__ void wcvt_kernel(WcvtParams p) {
    const int lvl = blockIdx.z;
    const int C = p.K[lvl];
    const int nW1 = 8 * (C / 32);
    const int t1 = blockIdx.x;
    const float* W;
    __half* out;
    int K, nb, kb;
    if (t1 < nW1) {
        W = p.W1[lvl]; K = C;
        out = g_W1h + p.w1off[lvl];
        nb = (t1 & 7) * 32; kb = (t1 >> 3) * 32;
    } else {
        const int t2 = t1 - nW1;
        if (t2 >= 64) return;
        W = p.W2[lvl]; K = NC;
        out = g_W2h + (size_t)lvl * 65536;
        nb = (t2 & 7) * 32; kb = (t2 >> 3) * 32;
    }
    const int tid = threadIdx.x;
    const int tx = tid & 31, ty = tid >> 5;
    __shared__ float t[32][33];
    for (int i = ty; i < 32; i += 8)
        t[i][tx] = W[(size_t)(kb + i) * NC + nb + tx];
    __syncthreads();
    for (int i = ty; i < 32; i += 8)
        out[(size_t)(nb + i) * K + kb + tx] = __float2half(t[tx][i]);
}

// ---------------- fused gather + MLP + l2norm ----------------
struct FusedParams {
    const float* feat[3];
    const void*  pid[3];
    const float* bias1[3];
    const float* bias2[3];
    int    C[3];
    int    HW[3];
    size_t w1off[3];
    float* out;
};

// one k16 MMA step: A and B both via non-trans ldmatrix from row-major-per-operand
// layouts (A: [M,k] stride strA; W: [N,K-slice] stride strW). Verified mapping (R6/R7):
// per 16-row N group, regs (r0,r2)=first n8, (r1,r3)=second n8.
__device__ __forceinline__ void mma_step16(
    uint32_t aBase, int strA, uint32_t aCol,
    uint32_t wBase, int strW, uint32_t wCol, int lr,
    float (&acc)[2][8][4])
{
    uint32_t a[2][4];
#pragma unroll
    for (int mt = 0; mt < 2; mt++)
        LDSM_X4(a[mt][0], a[mt][1], a[mt][2], a[mt][3],
                aBase + (mt * 16 + lr) * strA + aCol);
#pragma unroll
    for (int go = 0; go < 2; go++) {
        uint32_t b[2][4];
#pragma unroll
        for (int g = 0; g < 2; g++)
            LDSM_X4(b[g][0], b[g][1], b[g][2], b[g][3],
                    wBase + ((go * 2 + g) * 16 + lr) * strW + wCol);
#pragma unroll
        for (int mt = 0; mt < 2; mt++)
#pragma unroll
            for (int nl = 0; nl < 4; nl++) {
                const int nb = go * 4 + nl;
                const int g = nl >> 1, h = nl & 1;
                MMA16816(acc[mt][nb], a[mt], b[g][h], b[g][h + 2]);
            }
    }
}

__global__ void __launch_bounds__(256, 2) fused_kernel(FusedParams p) {
    extern __shared__ __align__(16) char dsm[];
    const uint32_t sb = smem_u32(dsm);

    const int lvl = blockIdx.z;
    const int K  = p.C[lvl];
    const int HW = p.HW[lvl];
    const int rowBase = blockIdx.x * TM;
    const int tid = threadIdx.x;
    const int wid = tid >> 5;
    const int lid = tid & 31;
    const int lr  = lid & 15;
    const int lcx = (lid >> 4) * 16;
    const int warpM = (wid >> 2) * 32;   // 0 / 32
    const int warpN = (wid & 3) * 64;    // 0..192

    const float* feat = p.feat[lvl];
    const __half* W1 = g_W1h + p.w1off[lvl];
    const __half* W2 = g_W2h + (size_t)lvl * 65536;
    size_t* srcb = (size_t*)(dsm + SRC_OFF);

    // ---- per-block row source offsets + rowsum init ----
    {
        const int* pw = (const int*)p.pid[lvl];
        bool i64 = true;
#pragma unroll
        for (int i = 1; i < 64; i += 2) i64 = i64 && (pw[i] == 0);
        if (tid < TM) {
            const int gr = rowBase + tid;
            long long pid = i64 ? ((const long long*)p.pid[lvl])[gr & 255]
                                : (long long)pw[gr & 255];
            if (pid < 0)  pid = 0;
            if (pid >= HW) pid = HW - 1;
            srcb[tid] = (size_t)(gr >> 8) * K * HW + (size_t)pid;
            *(float*)(dsm + RS_OFF + tid * 4) = 0.0f;
        }
    }
    __syncthreads();

    // ---- gather: 1024 (row, k-pair) jobs per stage, 4/thread ----
    float xg[4][2];
    auto gatherLDG = [&](int t) {
        const int k0 = t * KT;
#pragma unroll
        for (int j = 0; j < 4; j++) {
            const int pi = tid + 256 * j;
            const int row = pi >> 4;
            const int c = k0 + (pi & 15) * 2;
            const float* s = feat + srcb[row] + (size_t)c * HW;
            xg[j][0] = s[0];
            xg[j][1] = s[(size_t)HW];
        }
    };
    auto gatherSTS = [&](int buf) {
#pragma unroll
        for (int j = 0; j < 4; j++) {
            const int pi = tid + 256 * j;
            const int row = pi >> 4;
            __half2 h = __floats2half2_rn(xg[j][0], xg[j][1]);
            *(uint32_t*)(dsm + buf * STG + A_OFF + row * 80 + (pi & 15) * 4) =
                *(uint32_t*)&h;
        }
    };
    // W stage: 256 n-rows x 32 k fp16 = 1024 x 16B chunks, 4/thread
    auto loadW = [&](const __half* Wg, int t, int buf) {
        const int k0 = t * KT;
#pragma unroll
        for (int j = 0; j < 4; j++) {
            const int job = tid + 256 * j;          // 0..1023
            const int n = job >> 2, ch = job & 3;
            CP16(sb + buf * STG + W_OFF + n * 80 + ch * 16,
                 Wg + (size_t)n * K + k0 + ch * 8);
        }
        CP_COMMIT();
    };
    auto loadW2 = [&](int t, int buf) {
        const int k0 = t * KT;
#pragma unroll
        for (int j = 0; j < 4; j++) {
            const int job = tid + 256 * j;
            const int n = job >> 2, ch = job & 3;
            CP16(sb + buf * STG + W_OFF + n * 80 + ch * 16,
                 W2 + (size_t)n * 256 + k0 + ch * 8);
        }
        CP_COMMIT();
    };

    float acc[2][8][4];
#pragma unroll
    for (int mt = 0; mt < 2; mt++)
#pragma unroll
        for (int nb = 0; nb < 8; nb++)
#pragma unroll
            for (int j = 0; j < 4; j++) acc[mt][nb][j] = 0.0f;

    // ================= layer 1 (pipelined gather + W cp.async) ==============
    const int nk1 = K / KT;
    gatherLDG(0); loadW(W1, 0, 0); gatherSTS(0);
    for (int t = 0; t < nk1; t++) {
        const int buf = t & 1;
        const bool more = (t + 1 < nk1);
        if (more) { gatherLDG(t + 1); loadW(W1, t + 1, buf ^ 1); CP_WAIT1(); }
        else      { CP_WAIT0(); }
        __syncthreads();
        const uint32_t base = sb + buf * STG;
#pragma unroll
        for (int kk = 0; kk < 2; kk++)
            mma_step16(base + A_OFF + warpM * 80, 80, kk * 32 + lcx,
                       base + W_OFF + warpN * 80, 80, kk * 32 + lcx, lr, acc);
        if (more) gatherSTS(buf ^ 1);
        __syncthreads();
    }

    // prefetch W2 stage 0 (nk1 even -> buf0 free), epilogue-1: bias+relu -> H fp16
    loadW2(0, 0);
    {
        const float* b1 = p.bias1[lvl];
#pragma unroll
        for (int mt = 0; mt < 2; mt++)
#pragma unroll
            for (int nb = 0; nb < 8; nb++) {
                const int c = warpN + (lid & 3) * 2 + nb * 8;
                const float bx = b1[c], by = b1[c + 1];
#pragma unroll
                for (int hr = 0; hr < 2; hr++) {
                    const int r = warpM + mt * 16 + hr * 8 + (lid >> 2);
                    float v0 = fmaxf(acc[mt][nb][hr * 2]     + bx, 0.0f);
                    float v1 = fmaxf(acc[mt][nb][hr * 2 + 1] + by, 0.0f);
                    __half2 h = __floats2half2_rn(v0, v1);
                    *(uint32_t*)(dsm + H_OFF + r * 528 + c * 2) = *(uint32_t*)&h;
                }
            }
    }
#pragma unroll
    for (int mt = 0; mt < 2; mt++)
#pragma unroll
        for (int nb = 0; nb < 8; nb++)
#pragma unroll
            for (int j = 0; j < 4; j++) acc[mt][nb][j] = 0.0f;

    // ================= layer 2 (A = H smem, W2 cp.async, 8 stages) ==========
    for (int t = 0; t < 8; t++) {
        const int buf = t & 1;
        if (t + 1 < 8) { loadW2(t + 1, buf ^ 1); CP_WAIT1(); }
        else           { CP_WAIT0(); }
        __syncthreads();
        const uint32_t base = sb + buf * STG;
#pragma unroll
        for (int kk = 0; kk < 2; kk++)
            mma_step16(sb + H_OFF + warpM * 528, 528, (t * 32 + kk * 16) * 2 + lcx,
                       base + W_OFF + warpN * 80, 80, kk * 32 + lcx, lr, acc);
        __syncthreads();
    }

    // ============ epilogue-2: bias, row sum-of-squares, normalize, store =====
    {
        const float* b2 = p.bias2[lvl];
        float* rowsum = (float*)(dsm + RS_OFF);
#pragma unroll
        for (int mt = 0; mt < 2; mt++)
#pragma unroll
            for (int hr = 0; hr < 2; hr++) {
                float part = 0.0f;
#pragma unroll
                for (int nb = 0; nb < 8; nb++) {
                    const int c = warpN + (lid & 3) * 2 + nb * 8;
                    float v0 = acc[mt][nb][hr * 2]     + b2[c];
                    float v1 = acc[mt][nb][hr * 2 + 1] + b2[c + 1];
                    acc[mt][nb][hr * 2]     = v0;
                    acc[mt][nb][hr * 2 + 1] = v1;
                    part += v0 * v0 + v1 * v1;
                }
                atomicAdd(&rowsum[warpM + mt * 16 + hr * 8 + (lid >> 2)], part);
            }
        __syncthreads();
        float* O = p.out + (size_t)lvl * NROWS * NC;
#pragma unroll
        for (int mt = 0; mt < 2; mt++)
#pragma unroll
            for (int hr = 0; hr < 2; hr++) {
                const int r = warpM + mt * 16 + hr * 8 + (lid >> 2);
                const float sc = 1.0f / (sqrtf(rowsum[r]) + 1e-7f);
#pragma unroll
                for (int nb = 0; nb < 8; nb++) {
                    const int c = warpN + (lid & 3) * 2 + nb * 8;
                    float2 o;
                    o.x = acc[mt][nb][hr * 2]     * sc;
                    o.y = acc[mt][nb][hr * 2 + 1] * sc;
                    *(float2*)(O + (size_t)(rowBase + r) * NC + c) = o;
                }
            }
    }
}

// ---------------- host ----------------
#define F0 67108864LL
#define F1 33554432LL
#define F2 16777216LL
#define W10 65536LL
#define W11 131072LL
#define W12 262144LL
#define SB  256LL

static inline bool ok_sz(long long actual, long long elems) {
    return actual == elems || actual == elems * 4 || actual == elems * 8;
}

extern "C" void kernel_launch(void* const* d_in, const int* in_sizes, int n_in,
                              void* d_out, int out_size) {
    (void)out_size;
    static const int CS[3]  = {256, 512, 1024};
    static const int HWS[3] = {128 * 128, 64 * 64, 32 * 32};
    static const size_t W1OFF[3] = {0, (size_t)256 * 256, (size_t)256 * 768};

    static bool s_attr = false;
    if (!s_attr) {
        cudaFuncSetAttribute(fused_kernel,
                             cudaFuncAttributeMaxDynamicSharedMemorySize, SMEM_TOTAL);
        s_attr = true;
    }

    static const int ORD_DICT[18]  = { 0,1,2,3,4,5,  6,7,8,9,10,11,  12,13,14,15,16,17 };
    static const int ORD_SIG[18]   = { 0,3,6,7,8,9,  1,4,10,11,12,13,  2,5,14,15,16,17 };
    static const int ORD_ALPHA[18] = { 6,9,12,0,15,3,  7,10,13,1,16,4,  8,11,14,2,17,5 };

    const long long featsz[3] = { F0, F1, F2 };
    const long long w1sz[3]   = { W10, W11, W12 };

    const int* cand[3] = { ORD_DICT, ORD_SIG, ORD_ALPHA };
    const int* ord = nullptr;
    for (int c = 0; c < 3 && !ord; c++) {
        bool ok = (n_in >= 18);
        for (int l = 0; l < 3 && ok; l++) {
            const int* m = cand[c] + 6 * l;
            ok = ok && ok_sz(in_sizes[m[0]], featsz[l])
                    && ok_sz(in_sizes[m[1]], SB)
                    && ok_sz(in_sizes[m[2]], w1sz[l])
                    && ok_sz(in_sizes[m[3]], SB)
                    && ok_sz(in_sizes[m[4]], W10)
                    && ok_sz(in_sizes[m[5]], SB);
        }
        if (ok) ord = cand[c];
    }

    int fi[3] = {-1,-1,-1}, pi[3] = {-1,-1,-1}, w1i[3] = {-1,-1,-1};
    int b1i[3] = {-1,-1,-1}, w2i[3] = {-1,-1,-1}, b2i[3] = {-1,-1,-1};
    if (ord) {
        for (int l = 0; l < 3; l++) {
            const int* m = ord + 6 * l;
            fi[l] = m[0]; pi[l] = m[1]; w1i[l] = m[2];
            b1i[l] = m[3]; w2i[l] = m[4]; b2i[l] = m[5];
        }
    } else {
        int any256 = -1, w2seen = 0, w10seen = 0;
        for (int i = 0; i < n_in; i++) {
            long long s = in_sizes[i];
            if      (ok_sz(s, F0))  fi[0] = i;
            else if (ok_sz(s, F1))  fi[1] = i;
            else if (ok_sz(s, F2))  fi[2] = i;
            else if (ok_sz(s, W11)) w1i[1] = i;
            else if (ok_sz(s, W12)) w1i[2] = i;
            else if (ok_sz(s, W10)) {
                if (!w10seen) { w1i[0] = i; w10seen = 1; }
                else if (w2seen < 3) w2i[w2seen++] = i;
            }
            else if (ok_sz(s, SB) && any256 < 0) any256 = i;
        }
        for (int l = 0; l < 3; l++) {
            if (fi[l] >= 0) {
                int nxt = fi[l] + 1;
                pi[l] = (nxt < n_in && ok_sz(in_sizes[nxt], SB)) ? nxt : any256;
            }
            b1i[l] = any256; b2i[l] = any256;
        }
    }
    for (int l = 0; l < 3; l++) {
        if (fi[l] < 0 || pi[l] < 0 || w1i[l] < 0 || b1i[l] < 0 ||
            w2i[l] < 0 || b2i[l] < 0) return;
    }

    WcvtParams wc;
    FusedParams fp;
    for (int i = 0; i < 3; i++) {
        wc.W1[i] = (const float*)d_in[w1i[i]];
        wc.W2[i] = (const float*)d_in[w2i[i]];
        wc.K[i]  = CS[i];
        wc.w1off[i] = W1OFF[i];

        fp.feat[i]  = (const float*)d_in[fi[i]];
        fp.pid[i]   = d_in[pi[i]];
        fp.bias1[i] = (const float*)d_in[b1i[i]];
        fp.bias2[i] = (const float*)d_in[b2i[i]];
        fp.C[i]     = CS[i];
        fp.HW[i]    = HWS[i];
        fp.w1off[i] = W1OFF[i];
    }
    fp.out = (float*)d_out;

    // wcvt: worst level tiles = 8*(1024/32) + 64 = 320
    wcvt_kernel<<<dim3(320, 1, 3), 256>>>(wc);

    fused_kernel<<<dim3(NROWS / TM, 1, 3), 256, SMEM_TOTAL>>>(fp);
}

// round 11
// speedup vs baseline: 1.6106x; 1.2262x over previous
#include <cuda_runtime.h>
#include <cuda_fp16.h>
#include <math.h>
#include <stdint.h>

#define NROWS 4096
#define NC    256
#define TM    32            // rows per fused block
#define KT    32            // k per pipeline stage

// smem layout (bytes); all section bases 16B aligned
#define STG    23040        // stage: A 32x80 | W 256x80
#define A_OFF  0
#define W_OFF  2560
#define H_OFF  46080        // H: 32 rows x 528B (256 fp16 + pad)
#define RS_OFF 62976        // rowsum[32] float
#define SRC_OFF 63104       // srcbase[32] size_t
#define SMEM_TOTAL 63360

// ---------------- scratch: fp16 weights, TRANSPOSED [N=256, K] layout ----------------
__device__ __align__(16) __half g_W1h[256 * 1792];
__device__ __align__(16) __half g_W2h[3 * 256 * 256];

// ---------------- asm helpers ----------------
__device__ __forceinline__ uint32_t smem_u32(const void* p) {
    uint32_t a;
    asm("{ .reg .u64 t; cvta.to.shared.u64 t, %1; cvt.u32.u64 %0, t; }" : "=r"(a) : "l"(p));
    return a;
}
#define LDSM_X4(r0, r1, r2, r3, addr) \
    asm volatile("ldmatrix.sync.aligned.m8n8.x4.shared.b16 {%0,%1,%2,%3}, [%4];" \
        : "=r"(r0), "=r"(r1), "=r"(r2), "=r"(r3) : "r"(addr))
#define MMA16816(d, a, b0v, b1v) \
    asm volatile("mma.sync.aligned.m16n8k16.row.col.f32.f16.f16.f32 " \
        "{%0,%1,%2,%3}, {%4,%5,%6,%7}, {%8,%9}, {%0,%1,%2,%3};" \
        : "+f"((d)[0]), "+f"((d)[1]), "+f"((d)[2]), "+f"((d)[3]) \
        : "r"((a)[0]), "r"((a)[1]), "r"((a)[2]), "r"((a)[3]), "r"(b0v), "r"(b1v))
#define CP16(dst, src) \
    asm volatile("cp.async.cg.shared.global [%0], [%1], 16;" :: "r"(dst), "l"(src))
#define CP_COMMIT() asm volatile("cp.async.commit_group;" ::: "memory")
#define CP_WAIT0()  asm volatile("cp.async.wait_group 0;" ::: "memory")
#define CP_WAIT1()  asm volatile("cp.async.wait_group 1;" ::: "memory")

// ---------------- weight convert: fp32 [K,256] -> fp16 [256,K] (transpose) ----------------
struct WcvtParams {
    const float* W1[3];
    const float* W2[3];
    int    K[3];
    size_t w1off[3];
};

__global__ void wcvt_kernel(WcvtParams p) {
    const int lvl = blockIdx.z;
    const int C = p.K[lvl];
    const int nW1 = 8 * (C / 32);
    const int t1 = blockIdx.x;
    const float* W;
    __half* out;
    int K, nb, kb;
    if (t1 < nW1) {
        W = p.W1[lvl]; K = C;
        out = g_W1h + p.w1off[lvl];
        nb = (t1 & 7) * 32; kb = (t1 >> 3) * 32;
    } else {
        const int t2 = t1 - nW1;
        if (t2 >= 64) return;
        W = p.W2[lvl]; K = NC;
        out = g_W2h + (size_t)lvl * 65536;
        nb = (t2 & 7) * 32; kb = (t2 >> 3) * 32;
    }
    const int tid = threadIdx.x;
    const int tx = tid & 31, ty = tid >> 5;
    __shared__ float t[32][33];
    for (int i = ty; i < 32; i += 8)
        t[i][tx] = W[(size_t)(kb + i) * NC + nb + tx];
    __syncthreads();
    for (int i = ty; i < 32; i += 8)
        out[(size_t)(nb + i) * K + kb + tx] = __float2half(t[tx][i]);
}

// ---------------- fused gather + MLP + l2norm ----------------
struct FusedParams {
    const float* feat[3];
    const void*  pid[3];
    const float* bias1[3];
    const float* bias2[3];
    int    C[3];
    int    HW[3];
    size_t w1off[3];
    float* out;
};

// one k16 MMA step; verified mapping (R6/R7/R9): per 16-row N group,
// regs (r0,r2)=first n8, (r1,r3)=second n8. Warp M-tile = 16 rows.
__device__ __forceinline__ void mma_step16(
    uint32_t aBase, int strA, uint32_t aCol,
    uint32_t wBase, int strW, uint32_t wCol, int lr,
    float (&acc)[8][4])
{
    uint32_t a[4];
    LDSM_X4(a[0], a[1], a[2], a[3], aBase + lr * strA + aCol);
#pragma unroll
    for (int go = 0; go < 2; go++) {
        uint32_t b[2][4];
#pragma unroll
        for (int g = 0; g < 2; g++)
            LDSM_X4(b[g][0], b[g][1], b[g][2], b[g][3],
                    wBase + ((go * 2 + g) * 16 + lr) * strW + wCol);
#pragma unroll
        for (int nl = 0; nl < 4; nl++) {
            const int nb = go * 4 + nl;
            const int g = nl >> 1, h = nl & 1;
            MMA16816(acc[nb], a, b[g][h], b[g][h + 2]);
        }
    }
}

__global__ void __launch_bounds__(256, 3) fused_kernel(FusedParams p) {
    extern __shared__ __align__(16) char dsm[];
    const uint32_t sb = smem_u32(dsm);

    const int lvl = blockIdx.z;
    const int K  = p.C[lvl];
    const int HW = p.HW[lvl];
    const int rowBase = blockIdx.x * TM;
    const int tid = threadIdx.x;
    const int wid = tid >> 5;
    const int lid = tid & 31;
    const int lr  = lid & 15;
    const int lcx = (lid >> 4) * 16;
    const int warpM = (wid >> 2) * 16;   // 0 / 16
    const int warpN = (wid & 3) * 64;    // 0..192

    const float* feat = p.feat[lvl];
    const __half* W1 = g_W1h + p.w1off[lvl];
    const __half* W2 = g_W2h + (size_t)lvl * 65536;
    size_t* srcb = (size_t*)(dsm + SRC_OFF);

    // ---- per-block row source offsets + rowsum init ----
    {
        const int* pw = (const int*)p.pid[lvl];
        bool i64 = true;
#pragma unroll
        for (int i = 1; i < 64; i += 2) i64 = i64 && (pw[i] == 0);
        if (tid < TM) {
            const int gr = rowBase + tid;
            long long pid = i64 ? ((const long long*)p.pid[lvl])[gr & 255]
                                : (long long)pw[gr & 255];
            if (pid < 0)  pid = 0;
            if (pid >= HW) pid = HW - 1;
            srcb[tid] = (size_t)(gr >> 8) * K * HW + (size_t)pid;
            *(float*)(dsm + RS_OFF + tid * 4) = 0.0f;
        }
    }
    __syncthreads();

    // ---- gather: 512 (row, k-pair) jobs per stage, 2/thread (4 loads) ----
    float xg[2][2];
    auto gatherLDG = [&](int t) {
        const int k0 = t * KT;
#pragma unroll
        for (int j = 0; j < 2; j++) {
            const int pi = tid + 256 * j;
            const int row = pi >> 4;
            const int c = k0 + (pi & 15) * 2;
            const float* s = feat + srcb[row] + (size_t)c * HW;
            xg[j][0] = s[0];
            xg[j][1] = s[(size_t)HW];
        }
    };
    auto gatherSTS = [&](int buf) {
#pragma unroll
        for (int j = 0; j < 2; j++) {
            const int pi = tid + 256 * j;
            const int row = pi >> 4;
            __half2 h = __floats2half2_rn(xg[j][0], xg[j][1]);
            *(uint32_t*)(dsm + buf * STG + A_OFF + row * 80 + (pi & 15) * 4) =
                *(uint32_t*)&h;
        }
    };
    // W stage: 256 n-rows x 32 k fp16 = 1024 x 16B chunks, 4/thread
    auto loadW = [&](const __half* Wg, int t, int buf) {
        const int k0 = t * KT;
#pragma unroll
        for (int j = 0; j < 4; j++) {
            const int job = tid + 256 * j;          // 0..1023
            const int n = job >> 2, ch = job & 3;
            CP16(sb + buf * STG + W_OFF + n * 80 + ch * 16,
                 Wg + (size_t)n * K + k0 + ch * 8);
        }
        CP_COMMIT();
    };
    auto loadW2 = [&](int t, int buf) {
        const int k0 = t * KT;
#pragma unroll
        for (int j = 0; j < 4; j++) {
            const int job = tid + 256 * j;
            const int n = job >> 2, ch = job & 3;
            CP16(sb + buf * STG + W_OFF + n * 80 + ch * 16,
                 W2 + (size_t)n * 256 + k0 + ch * 8);
        }
        CP_COMMIT();
    };

    float acc[8][4];
#pragma unroll
    for (int nb = 0; nb < 8; nb++)
#pragma unroll
        for (int j = 0; j < 4; j++) acc[nb][j] = 0.0f;

    // ================= layer 1 (pipelined gather + W cp.async) ==============
    const int nk1 = K / KT;
    gatherLDG(0); loadW(W1, 0, 0); gatherSTS(0);
    for (int t = 0; t < nk1; t++) {
        const int buf = t & 1;
        const bool more = (t + 1 < nk1);
        if (more) { gatherLDG(t + 1); loadW(W1, t + 1, buf ^ 1); CP_WAIT1(); }
        else      { CP_WAIT0(); }
        __syncthreads();
        const uint32_t base = sb + buf * STG;
#pragma unroll
        for (int kk = 0; kk < 2; kk++)
            mma_step16(base + A_OFF + warpM * 80, 80, kk * 32 + lcx,
                       base + W_OFF + warpN * 80, 80, kk * 32 + lcx, lr, acc);
        if (more) gatherSTS(buf ^ 1);
        __syncthreads();
    }

    // prefetch W2 stage 0 (nk1 even -> buf0 free), epilogue-1: bias+relu -> H fp16
    loadW2(0, 0);
    {
        const float* b1 = p.bias1[lvl];
#pragma unroll
        for (int nb = 0; nb < 8; nb++) {
            const int c = warpN + (lid & 3) * 2 + nb * 8;
            const float bx = b1[c], by = b1[c + 1];
#pragma unroll
            for (int hr = 0; hr < 2; hr++) {
                const int r = warpM + hr * 8 + (lid >> 2);
                float v0 = fmaxf(acc[nb][hr * 2]     + bx, 0.0f);
                float v1 = fmaxf(acc[nb][hr * 2 + 1] + by, 0.0f);
                __half2 h = __floats2half2_rn(v0, v1);
                *(uint32_t*)(dsm + H_OFF + r * 528 + c * 2) = *(uint32_t*)&h;
            }
        }
    }
#pragma unroll
    for (int nb = 0; nb < 8; nb++)
#pragma unroll
        for (int j = 0; j < 4; j++) acc[nb][j] = 0.0f;

    // ================= layer 2 (A = H smem, W2 cp.async, 8 stages) ==========
    for (int t = 0; t < 8; t++) {
        const int buf = t & 1;
        if (t + 1 < 8) { loadW2(t + 1, buf ^ 1); CP_WAIT1(); }
        else           { CP_WAIT0(); }
        __syncthreads();
        const uint32_t base = sb + buf * STG;
#pragma unroll
        for (int kk = 0; kk < 2; kk++)
            mma_step16(sb + H_OFF + warpM * 528, 528, (t * 32 + kk * 16) * 2 + lcx,
                       base + W_OFF + warpN * 80, 80, kk * 32 + lcx, lr, acc);
        __syncthreads();
    }

    // ============ epilogue-2: bias, row sum-of-squares, normalize, store =====
    {
        const float* b2 = p.bias2[lvl];
        float* rowsum = (float*)(dsm + RS_OFF);
#pragma unroll
        for (int hr = 0; hr < 2; hr++) {
            float part = 0.0f;
#pragma unroll
            for (int nb = 0; nb < 8; nb++) {
                const int c = warpN + (lid & 3) * 2 + nb * 8;
                float v0 = acc[nb][hr * 2]     + b2[c];
                float v1 = acc[nb][hr * 2 + 1] + b2[c + 1];
                acc[nb][hr * 2]     = v0;
                acc[nb][hr * 2 + 1] = v1;
                part += v0 * v0 + v1 * v1;
            }
            atomicAdd(&rowsum[warpM + hr * 8 + (lid >> 2)], part);
        }
        __syncthreads();
        float* O = p.out + (size_t)lvl * NROWS * NC;
#pragma unroll
        for (int hr = 0; hr < 2; hr++) {
            const int r = warpM + hr * 8 + (lid >> 2);
            const float sc = 1.0f / (sqrtf(rowsum[r]) + 1e-7f);
#pragma unroll
            for (int nb = 0; nb < 8; nb++) {
                const int c = warpN + (lid & 3) * 2 + nb * 8;
                float2 o;
                o.x = acc[nb][hr * 2]     * sc;
                o.y = acc[nb][hr * 2 + 1] * sc;
                *(float2*)(O + (size_t)(rowBase + r) * NC + c) = o;
            }
        }
    }
}

// ---------------- host ----------------
#define F0 67108864LL
#define F1 33554432LL
#define F2 16777216LL
#define W10 65536LL
#define W11 131072LL
#define W12 262144LL
#define SB  256LL

static inline bool ok_sz(long long actual, long long elems) {
    return actual == elems || actual == elems * 4 || actual == elems * 8;
}

extern "C" void kernel_launch(void* const* d_in, const int* in_sizes, int n_in,
                              void* d_out, int out_size) {
    (void)out_size;
    static const int CS[3]  = {256, 512, 1024};
    static const int HWS[3] = {128 * 128, 64 * 64, 32 * 32};
    static const size_t W1OFF[3] = {0, (size_t)256 * 256, (size_t)256 * 768};

    static bool s_attr = false;
    if (!s_attr) {
        cudaFuncSetAttribute(fused_kernel,
                             cudaFuncAttributeMaxDynamicSharedMemorySize, SMEM_TOTAL);
        s_attr = true;
    }

    static const int ORD_DICT[18]  = { 0,1,2,3,4,5,  6,7,8,9,10,11,  12,13,14,15,16,17 };
    static const int ORD_SIG[18]   = { 0,3,6,7,8,9,  1,4,10,11,12,13,  2,5,14,15,16,17 };
    static const int ORD_ALPHA[18] = { 6,9,12,0,15,3,  7,10,13,1,16,4,  8,11,14,2,17,5 };

    const long long featsz[3] = { F0, F1, F2 };
    const long long w1sz[3]   = { W10, W11, W12 };

    const int* cand[3] = { ORD_DICT, ORD_SIG, ORD_ALPHA };
    const int* ord = nullptr;
    for (int c = 0; c < 3 && !ord; c++) {
        bool ok = (n_in >= 18);
        for (int l = 0; l < 3 && ok; l++) {
            const int* m = cand[c] + 6 * l;
            ok = ok && ok_sz(in_sizes[m[0]], featsz[l])
                    && ok_sz(in_sizes[m[1]], SB)
                    && ok_sz(in_sizes[m[2]], w1sz[l])
                    && ok_sz(in_sizes[m[3]], SB)
                    && ok_sz(in_sizes[m[4]], W10)
                    && ok_sz(in_sizes[m[5]], SB);
        }
        if (ok) ord = cand[c];
    }

    int fi[3] = {-1,-1,-1}, pi[3] = {-1,-1,-1}, w1i[3] = {-1,-1,-1};
    int b1i[3] = {-1,-1,-1}, w2i[3] = {-1,-1,-1}, b2i[3] = {-1,-1,-1};
    if (ord) {
        for (int l = 0; l < 3; l++) {
            const int* m = ord + 6 * l;
            fi[l] = m[0]; pi[l] = m[1]; w1i[l] = m[2];
            b1i[l] = m[3]; w2i[l] = m[4]; b2i[l] = m[5];
        }
    } else {
        int any256 = -1, w2seen = 0, w10seen = 0;
        for (int i = 0; i < n_in; i++) {
            long long s = in_sizes[i];
            if      (ok_sz(s, F0))  fi[0] = i;
            else if (ok_sz(s, F1))  fi[1] = i;
            else if (ok_sz(s, F2))  fi[2] = i;
            else if (ok_sz(s, W11)) w1i[1] = i;
            else if (ok_sz(s, W12)) w1i[2] = i;
            else if (ok_sz(s, W10)) {
                if (!w10seen) { w1i[0] = i; w10seen = 1; }
                else if (w2seen < 3) w2i[w2seen++] = i;
            }
            else if (ok_sz(s, SB) && any256 < 0) any256 = i;
        }
        for (int l = 0; l < 3; l++) {
            if (fi[l] >= 0) {
                int nxt = fi[l] + 1;
                pi[l] = (nxt < n_in && ok_sz(in_sizes[nxt], SB)) ? nxt : any256;
            }
            b1i[l] = any256; b2i[l] = any256;
        }
    }
    for (int l = 0; l < 3; l++) {
        if (fi[l] < 0 || pi[l] < 0 || w1i[l] < 0 || b1i[l] < 0 ||
            w2i[l] < 0 || b2i[l] < 0) return;
    }

    WcvtParams wc;
    FusedParams fp;
    for (int i = 0; i < 3; i++) {
        wc.W1[i] = (const float*)d_in[w1i[i]];
        wc.W2[i] = (const float*)d_in[w2i[i]];
        wc.K[i]  = CS[i];
        wc.w1off[i] = W1OFF[i];

        fp.feat[i]  = (const float*)d_in[fi[i]];
        fp.pid[i]   = d_in[pi[i]];
        fp.bias1[i] = (const float*)d_in[b1i[i]];
        fp.bias2[i] = (const float*)d_in[b2i[i]];
        fp.C[i]     = CS[i];
        fp.HW[i]    = HWS[i];
        fp.w1off[i] = W1OFF[i];
    }
    fp.out = (float*)d_out;

    // wcvt: worst level tiles = 8*(1024/32) + 64 = 320
    wcvt_kernel<<<dim3(320, 1, 3), 256>>>(wc);

    fused_kernel<<<dim3(NROWS / TM, 1, 3), 256, SMEM_TOTAL>>>(fp);
}